// round 8
// baseline (speedup 1.0000x reference)
#include <cuda_runtime.h>
#include <cuda_bf16.h>
#include <math.h>
#include <cstdint>

#define DIMC 256
#define HEADS 8
#define WSZ 8
#define SSZ 4
#define BATCH 16
#define IMG 64
#define ROWS (BATCH*IMG*IMG)   /* 65536 token rows */
#define QSCALE 0.17677669529663687f

typedef __nv_bfloat16 bf16;

// ---------------- scratch (device globals; no allocation allowed) ----------------
__device__ __align__(16) bf16  g_xw  [ROWS*DIMC];      // LN1 + shift + window partition
__device__ __align__(16) bf16  g_qkv [ROWS*3*DIMC];    // qkv projections
__device__ __align__(16) bf16  g_attn[ROWS*DIMC];      // attention output (window layout)
__device__ __align__(16) bf16  g_yn  [ROWS*DIMC];      // LN2(x + proj)
__device__ __align__(16) bf16  g_m1  [ROWS*4*DIMC];    // gelu(fc1)
// transposed weights  WT[n*K + k] = W[k*N + n]   (bf16)
__device__ __align__(16) bf16 g_wt_qkv [768*256];
__device__ __align__(16) bf16 g_wt_proj[256*256];
__device__ __align__(16) bf16 g_wt_fc1 [1024*256];
__device__ __align__(16) bf16 g_wt_fc2 [256*1024];

// ---------------- helpers --------------------------------------------------------
__device__ __forceinline__ uint32_t smem_u32(const void* p) {
    uint32_t a;
    asm("{ .reg .u64 t; cvta.to.shared.u64 t, %1; cvt.u32.u64 %0, t; }" : "=r"(a) : "l"(p));
    return a;
}
#define CP_ASYNC16(dst, src) \
    asm volatile("cp.async.cg.shared.global [%0], [%1], 16;" :: "r"(dst), "l"(src))
#define CP_COMMIT() asm volatile("cp.async.commit_group;")
#define CP_WAIT1()  asm volatile("cp.async.wait_group 1;")
#define CP_WAIT0()  asm volatile("cp.async.wait_group 0;")

__device__ __forceinline__ void mma_bf16(float c[4], uint32_t a0, uint32_t a1,
                                         uint32_t a2, uint32_t a3,
                                         uint32_t b0, uint32_t b1) {
    asm volatile(
        "mma.sync.aligned.m16n8k16.row.col.f32.bf16.bf16.f32 "
        "{%0,%1,%2,%3}, {%4,%5,%6,%7}, {%8,%9}, {%0,%1,%2,%3};"
        : "+f"(c[0]), "+f"(c[1]), "+f"(c[2]), "+f"(c[3])
        : "r"(a0), "r"(a1), "r"(a2), "r"(a3), "r"(b0), "r"(b1));
}
__device__ __forceinline__ void ldmat_x4(uint32_t r[4], uint32_t saddr) {
    asm volatile("ldmatrix.sync.aligned.m8n8.x4.shared.b16 {%0,%1,%2,%3}, [%4];"
                 : "=r"(r[0]), "=r"(r[1]), "=r"(r[2]), "=r"(r[3]) : "r"(saddr));
}
__device__ __forceinline__ uint32_t pack_bf16x2(float lo, float hi) {
    __nv_bfloat162 h = __floats2bfloat162_rn(lo, hi);
    return *(uint32_t*)&h;
}

// ---------------- LayerNorm: one warp per row, float4 loads, bf16 out -----------
__global__ void ln_kernel(const float* __restrict__ in, const float* __restrict__ g,
                          const float* __restrict__ b, bf16* __restrict__ out,
                          int shiftmode)
{
    int o = (blockIdx.x * blockDim.x + threadIdx.x) >> 5;   // row
    int lane = threadIdx.x & 31;
    int src = o;
    if (shiftmode) {
        int widx = o >> 6, n = o & 63;
        int bb = widx >> 6, wi = widx & 63;
        int wy = wi >> 3, wx = wi & 7;
        int iy = n >> 3,  ix = n & 7;
        int sh = (wy*8 + iy + SSZ) & 63;
        int sw = (wx*8 + ix + SSZ) & 63;
        src = bb*4096 + sh*64 + sw;
    }
    const float4* p = (const float4*)(in + (size_t)src*DIMC + lane*8);
    float4 v0 = p[0], v1 = p[1];
    float s  = v0.x+v0.y+v0.z+v0.w + v1.x+v1.y+v1.z+v1.w;
    float s2 = v0.x*v0.x+v0.y*v0.y+v0.z*v0.z+v0.w*v0.w
             + v1.x*v1.x+v1.y*v1.y+v1.z*v1.z+v1.w*v1.w;
    #pragma unroll
    for (int off = 16; off; off >>= 1) {
        s  += __shfl_xor_sync(0xffffffffu, s,  off);
        s2 += __shfl_xor_sync(0xffffffffu, s2, off);
    }
    float mean = s * (1.f/DIMC);
    float var  = s2 * (1.f/DIMC) - mean*mean;
    float r = rsqrtf(var + 1e-5f);
    const float4* gp = (const float4*)(g + lane*8);
    const float4* bp = (const float4*)(b + lane*8);
    float4 g0 = gp[0], g1 = gp[1], b0 = bp[0], b1 = bp[1];
    union { uint4 u; bf16 h[8]; } res;
    res.h[0] = __float2bfloat16((v0.x-mean)*r*g0.x + b0.x);
    res.h[1] = __float2bfloat16((v0.y-mean)*r*g0.y + b0.y);
    res.h[2] = __float2bfloat16((v0.z-mean)*r*g0.z + b0.z);
    res.h[3] = __float2bfloat16((v0.w-mean)*r*g0.w + b0.w);
    res.h[4] = __float2bfloat16((v1.x-mean)*r*g1.x + b1.x);
    res.h[5] = __float2bfloat16((v1.y-mean)*r*g1.y + b1.y);
    res.h[6] = __float2bfloat16((v1.z-mean)*r*g1.z + b1.z);
    res.h[7] = __float2bfloat16((v1.w-mean)*r*g1.w + b1.w);
    *(uint4*)(out + (size_t)o*DIMC + lane*8) = res.u;
}

// -------- merged weight transposes (+ bf16 round): WT[n*K+k] = W[k*N+n] ---------
__global__ void transpose_all(const float* __restrict__ qkv_w, bf16* __restrict__ wt_qkv,
                              const float* __restrict__ proj_w, bf16* __restrict__ wt_proj,
                              const float* __restrict__ fc1_w, bf16* __restrict__ wt_fc1,
                              const float* __restrict__ fc2_w, bf16* __restrict__ wt_fc2)
{
    int b = blockIdx.x;
    const float* w; bf16* wt; int K, N, tile;
    if (b < 192)      { w = qkv_w;  wt = wt_qkv;  K = 256;  N = 768;  tile = b; }
    else if (b < 256) { w = proj_w; wt = wt_proj; K = 256;  N = 256;  tile = b - 192; }
    else if (b < 512) { w = fc1_w;  wt = wt_fc1;  K = 256;  N = 1024; tile = b - 256; }
    else              { w = fc2_w;  wt = wt_fc2;  K = 1024; N = 256;  tile = b - 512; }
    int ntx = N / 32;
    int n0 = (tile % ntx) * 32, k0 = (tile / ntx) * 32;
    __shared__ float t[32][33];
    int tx = threadIdx.x, ty = threadIdx.y;   // 32 x 8
    #pragma unroll
    for (int i = ty; i < 32; i += 8) t[i][tx] = w[(size_t)(k0+i)*N + n0 + tx];
    __syncthreads();
    #pragma unroll
    for (int i = ty; i < 32; i += 8)
        wt[(size_t)(n0+i)*K + k0 + tx] = __float2bfloat16(t[tx][i]);
}

// ============ bf16 mma.sync GEMM: 128x128x64 tiles, 3-stage cp.async ============
// lookahead 2 (fills {t+2} while consuming t) — stage (t+2)%3 was consumed at t-1.
// MODE 0: bf16(+bias)    MODE 1: bf16(gelu(+bias))    MODE 3: f32: res+bias
#define PADH2 72                      /* halves per 64-half row in smem */
#define ASTG2 (128*PADH2*2)           /* bytes per stage per operand = 18432 */
template<int MODE, typename OutT>
__global__ __launch_bounds__(256, 2)
void mma_gemm(const bf16* __restrict__ A, const bf16* __restrict__ BT,
              const float* __restrict__ bias, const float* __restrict__ res,
              OutT* __restrict__ C, int M, int N, int K)
{
    extern __shared__ char smem[];   // A stages [0..2] | B stages [0..2]
    int tid = threadIdx.x, wid = tid >> 5, lane = tid & 31;
    int g = lane >> 2, ct = lane & 3;
    int wm = wid & 1, wn = wid >> 1;          // 2 x 4 warp grid
    int bm = blockIdx.y * 128, bn = blockIdx.x * 128;
    const bf16* Ab = A  + (size_t)bm * K;
    const bf16* Bb = BT + (size_t)bn * K;
    const int T = K / 64;

    int f_row = tid >> 1;
    int f_cb  = (tid & 1) * 4;       // 4 chunks of 16B per thread per operand

    #define FILL(t, s) do { \
        char* as_ = smem + (s)*ASTG2; \
        char* bs_ = smem + 3*ASTG2 + (s)*ASTG2; \
        _Pragma("unroll") \
        for (int i = 0; i < 4; i++) { \
            int c = f_cb + i; \
            CP_ASYNC16(smem_u32(as_ + f_row*(PADH2*2) + c*16), \
                       Ab + (size_t)f_row*K + (t)*64 + c*8); \
            CP_ASYNC16(smem_u32(bs_ + f_row*(PADH2*2) + c*16), \
                       Bb + (size_t)f_row*K + (t)*64 + c*8); \
        } \
        CP_COMMIT(); \
    } while (0)

    float acc[4][4][4];
    #pragma unroll
    for (int i = 0; i < 4; i++)
        #pragma unroll
        for (int j = 0; j < 4; j++)
            #pragma unroll
            for (int e = 0; e < 4; e++) acc[i][j][e] = 0.f;

    FILL(0, 0);
    if (T > 1) FILL(1, 1);

    int a_roff = (lane & 15);
    int a_koff = (lane >> 4) * 8;
    int b_roff = ((lane >> 4) & 1) * 8 + (lane & 7);
    int b_koff = ((lane >> 3) & 1) * 8;

    for (int t = 0; t < T; t++) {
        int rem = T - 1 - t;
        if (rem >= 1) CP_WAIT1(); else CP_WAIT0();
        __syncthreads();
        if (t + 2 < T) FILL(t + 2, (t + 2) % 3);

        int s = t % 3;
        const bf16* Ap = (const bf16*)(smem + s*ASTG2);
        const bf16* Bp = (const bf16*)(smem + 3*ASTG2 + s*ASTG2);
        #pragma unroll
        for (int ks = 0; ks < 4; ks++) {
            int k = ks*16;
            uint32_t af[4][4], bfr[2][4];
            #pragma unroll
            for (int tm = 0; tm < 4; tm++)
                ldmat_x4(af[tm], smem_u32(Ap + (wm*64 + tm*16 + a_roff)*PADH2 + k + a_koff));
            #pragma unroll
            for (int tnp = 0; tnp < 2; tnp++)
                ldmat_x4(bfr[tnp], smem_u32(Bp + (wn*32 + tnp*16 + b_roff)*PADH2 + k + b_koff));
            #pragma unroll
            for (int tm = 0; tm < 4; tm++)
                #pragma unroll
                for (int tnp = 0; tnp < 2; tnp++) {
                    mma_bf16(acc[tm][2*tnp],   af[tm][0], af[tm][1], af[tm][2], af[tm][3],
                             bfr[tnp][0], bfr[tnp][1]);
                    mma_bf16(acc[tm][2*tnp+1], af[tm][0], af[tm][1], af[tm][2], af[tm][3],
                             bfr[tnp][2], bfr[tnp][3]);
                }
        }
    }
    #undef FILL

    // ---- epilogue ----
    #pragma unroll
    for (int tm = 0; tm < 4; tm++) {
        int r0 = bm + wm*64 + tm*16 + g;
        #pragma unroll
        for (int half = 0; half < 2; half++) {
            int r = r0 + half*8;
            size_t dst = r;
            #pragma unroll
            for (int tn = 0; tn < 4; tn++) {
                int col = bn + wn*32 + tn*8 + ct*2;
                float v0 = acc[tm][tn][half*2]     + bias[col];
                float v1 = acc[tm][tn][half*2 + 1] + bias[col + 1];
                if (MODE == 1) {
                    v0 = 0.5f * v0 * (1.f + erff(v0 * 0.7071067811865475f));
                    v1 = 0.5f * v1 * (1.f + erff(v1 * 0.7071067811865475f));
                }
                if (MODE == 3) {
                    const float2 rr = *(const float2*)(res + dst*(size_t)N + col);
                    v0 += rr.x; v1 += rr.y;
                    *(float2*)((float*)C + dst*(size_t)N + col) = make_float2(v0, v1);
                } else {
                    __nv_bfloat162 h = __floats2bfloat162_rn(v0, v1);
                    *(__nv_bfloat162*)((bf16*)C + dst*(size_t)N + col) = h;
                }
            }
        }
    }
}

// ====== fused proj GEMM + window-reverse/shift scatter + residual + LN2 =========
#define PADH 40
#define PSTG_A (128*PADH*2)          /* 10240 B */
#define PSTG_B (256*PADH*2)          /* 20480 B */
#define PSTG   (PSTG_A + PSTG_B)
__global__ __launch_bounds__(256, 1)
void proj_ln_kernel(const bf16* __restrict__ A, const bf16* __restrict__ BT,
                    const float* __restrict__ bias, const float* __restrict__ x,
                    const float* __restrict__ g2, const float* __restrict__ b2,
                    bf16* __restrict__ yn)
{
    extern __shared__ char smem[];   // 3 stages of (A | B)
    const int K = 256, T = 8;
    int tid = threadIdx.x, wid = tid >> 5, lane = tid & 31;
    int g = lane >> 2, ct = lane & 3;
    int wm = wid & 1, wn = wid >> 1;          // 2 x 4: 64 rows x 64 cols per warp
    int bm = blockIdx.x * 128;
    const bf16* Ab = A + (size_t)bm * K;

    int f_row = tid >> 1;
    int f_cb  = (tid & 1) * 2;

    #define PFILL(t, s) do { \
        char* as_ = smem + (s)*PSTG; \
        char* bs_ = as_ + PSTG_A; \
        _Pragma("unroll") \
        for (int i = 0; i < 2; i++) { \
            int c = f_cb + i; \
            CP_ASYNC16(smem_u32(as_ + f_row*(PADH*2) + c*16), \
                       Ab + (size_t)f_row*K + (t)*32 + c*8); \
            CP_ASYNC16(smem_u32(bs_ + f_row*(PADH*2) + c*16), \
                       BT + (size_t)f_row*K + (t)*32 + c*8); \
            CP_ASYNC16(smem_u32(bs_ + (f_row+128)*(PADH*2) + c*16), \
                       BT + (size_t)(f_row+128)*K + (t)*32 + c*8); \
        } \
        CP_COMMIT(); \
    } while (0)

    float acc[4][8][4];
    #pragma unroll
    for (int i = 0; i < 4; i++)
        #pragma unroll
        for (int j = 0; j < 8; j++)
            #pragma unroll
            for (int e = 0; e < 4; e++) acc[i][j][e] = 0.f;

    PFILL(0, 0); PFILL(1, 1);

    int a_roff = (lane & 15);
    int a_koff = (lane >> 4) * 8;
    int b_roff = ((lane >> 4) & 1) * 8 + (lane & 7);
    int b_koff = ((lane >> 3) & 1) * 8;

    for (int t = 0; t < T; t++) {
        int rem = T - 1 - t;
        if (rem >= 1) CP_WAIT1(); else CP_WAIT0();
        __syncthreads();
        if (t + 2 < T) PFILL(t + 2, (t + 2) % 3);

        int s = t % 3;
        const bf16* Ap = (const bf16*)(smem + s*PSTG);
        const bf16* Bp = (const bf16*)(smem + s*PSTG + PSTG_A);
        #pragma unroll
        for (int ks = 0; ks < 2; ks++) {
            int k = ks*16;
            uint32_t af[4][4];
            #pragma unroll
            for (int tm = 0; tm < 4; tm++)
                ldmat_x4(af[tm], smem_u32(Ap + (wm*64 + tm*16 + a_roff)*PADH + k + a_koff));
            #pragma unroll
            for (int tnp = 0; tnp < 4; tnp++) {
                uint32_t bfr[4];
                ldmat_x4(bfr, smem_u32(Bp + (wn*64 + tnp*16 + b_roff)*PADH + k + b_koff));
                #pragma unroll
                for (int tm = 0; tm < 4; tm++) {
                    mma_bf16(acc[tm][2*tnp],   af[tm][0], af[tm][1], af[tm][2], af[tm][3],
                             bfr[0], bfr[1]);
                    mma_bf16(acc[tm][2*tnp+1], af[tm][0], af[tm][1], af[tm][2], af[tm][3],
                             bfr[2], bfr[3]);
                }
            }
        }
    }
    #undef PFILL

    // ---- epilogue: v = acc + bias + x[dst]; row LN; yn[dst] = LN(v) -------------
    float s1[8], s2a[8];
    size_t dsts[8];
    float2 bi[8];
    #pragma unroll
    for (int tn = 0; tn < 8; tn++)
        bi[tn] = *(const float2*)(bias + wn*64 + tn*8 + ct*2);

    #pragma unroll
    for (int tm = 0; tm < 4; tm++) {
        #pragma unroll
        for (int half = 0; half < 2; half++) {
            int rr = tm*2 + half;
            int r = bm + wm*64 + tm*16 + g + half*8;
            int widx = r >> 6, n = r & 63;
            int bb2 = widx >> 6, wi = widx & 63;
            int wy = wi >> 3, wx = wi & 7;
            int iy = n >> 3,  ix = n & 7;
            int dh = (wy*8 + iy + SSZ) & 63;
            int dw = (wx*8 + ix + SSZ) & 63;
            size_t dst = (size_t)(bb2*4096 + dh*64 + dw);
            dsts[rr] = dst;
            float s = 0.f, ss = 0.f;
            #pragma unroll
            for (int tn = 0; tn < 8; tn++) {
                int col = wn*64 + tn*8 + ct*2;
                float2 xr = *(const float2*)(x + dst*(size_t)DIMC + col);
                float v0 = acc[tm][tn][half*2]     + bi[tn].x + xr.x;
                float v1 = acc[tm][tn][half*2 + 1] + bi[tn].y + xr.y;
                acc[tm][tn][half*2] = v0; acc[tm][tn][half*2+1] = v1;
                s += v0 + v1; ss += v0*v0 + v1*v1;
            }
            s1[rr] = s; s2a[rr] = ss;
        }
    }
    #pragma unroll
    for (int rr = 0; rr < 8; rr++) {
        #pragma unroll
        for (int off = 1; off <= 2; off <<= 1) {
            s1[rr]  += __shfl_xor_sync(0xffffffffu, s1[rr],  off);
            s2a[rr] += __shfl_xor_sync(0xffffffffu, s2a[rr], off);
        }
    }
    __syncthreads();
    float* part = (float*)smem;
    if (ct == 0) {
        #pragma unroll
        for (int rr = 0; rr < 8; rr++) {
            int tm = rr >> 1, half = rr & 1;
            int rl = wm*64 + tm*16 + g + half*8;
            part[(rl*4 + wn)*2]     = s1[rr];
            part[(rl*4 + wn)*2 + 1] = s2a[rr];
        }
    }
    __syncthreads();

    float2 gg[8], bb[8];
    #pragma unroll
    for (int tn = 0; tn < 8; tn++) {
        int col = wn*64 + tn*8 + ct*2;
        gg[tn] = *(const float2*)(g2 + col);
        bb[tn] = *(const float2*)(b2 + col);
    }
    #pragma unroll
    for (int tm = 0; tm < 4; tm++) {
        #pragma unroll
        for (int half = 0; half < 2; half++) {
            int rr = tm*2 + half;
            int rl = wm*64 + tm*16 + g + half*8;
            float s = 0.f, ss = 0.f;
            #pragma unroll
            for (int w = 0; w < 4; w++) {
                s  += part[(rl*4 + w)*2];
                ss += part[(rl*4 + w)*2 + 1];
            }
            float mean = s * (1.f/DIMC);
            float var  = ss * (1.f/DIMC) - mean*mean;
            float rinv = rsqrtf(var + 1e-5f);
            size_t dst = dsts[rr];
            #pragma unroll
            for (int tn = 0; tn < 8; tn++) {
                int col = wn*64 + tn*8 + ct*2;
                float v0 = (acc[tm][tn][half*2]     - mean)*rinv*gg[tn].x + bb[tn].x;
                float v1 = (acc[tm][tn][half*2 + 1] - mean)*rinv*gg[tn].y + bb[tn].y;
                *(__nv_bfloat162*)(yn + dst*(size_t)DIMC + col) =
                    __floats2bfloat162_rn(v0, v1);
            }
        }
    }
}

// ======== tensor-core windowed attention: block = (window, head), 4 warps =======
__global__ __launch_bounds__(128)
void attn_kernel(const bf16* __restrict__ qkv, const float* __restrict__ rpb,
                 bf16* __restrict__ out)
{
    int bid  = blockIdx.x;      // widx*8 + head
    int head = bid & 7;
    int widx = bid >> 3;
    int wi = widx & 63;
    int wy = wi >> 3, wx = wi & 7;

    __shared__ bf16 qs[64*40];
    __shared__ bf16 ksm[64*40];
    __shared__ bf16 vt[32*72];
    __shared__ int  regid[64];
    __shared__ float rpbh[225];

    int tid = threadIdx.x, wid = tid >> 5, lane = tid & 31;
    int g = lane >> 2, ct = lane & 3;

    #pragma unroll
    for (int i = 0; i < 2; i++) {
        int idx = tid + i*128;
        int t = idx >> 2, ch = idx & 3;
        size_t base = (size_t)(widx*64 + t) * (3*DIMC) + head*32 + ch*8;
        uint4 qv = *(const uint4*)(qkv + base);
        uint4 kv = *(const uint4*)(qkv + base + DIMC);
        uint4 vv = *(const uint4*)(qkv + base + 2*DIMC);
        *(uint4*)(qs  + t*40 + ch*8) = qv;
        *(uint4*)(ksm + t*40 + ch*8) = kv;
        const bf16* vp = (const bf16*)&vv;
        #pragma unroll
        for (int j = 0; j < 8; j++) vt[(ch*8 + j)*72 + t] = vp[j];
    }
    for (int i = tid; i < 225; i += 128) rpbh[i] = rpb[i*HEADS + head];
    if (tid < 64) {
        int iy = tid >> 3, ix = tid & 7;
        int rh = (wy < 7) ? 0 : ((iy < SSZ) ? 1 : 2);
        int rw = (wx < 7) ? 0 : ((ix < SSZ) ? 1 : 2);
        regid[tid] = rh*3 + rw;
    }
    __syncthreads();

    int a_roff = (lane & 15);
    int a_koff = (lane >> 4) * 8;
    int b_roff = ((lane >> 4) & 1) * 8 + (lane & 7);
    int b_koff = ((lane >> 3) & 1) * 8;

    uint32_t qa[2][4];
    #pragma unroll
    for (int ks = 0; ks < 2; ks++)
        ldmat_x4(qa[ks], smem_u32(qs + (wid*16 + a_roff)*40 + ks*16 + a_koff));

    float S[8][4];
    #pragma unroll
    for (int tn = 0; tn < 8; tn++)
        #pragma unroll
        for (int e = 0; e < 4; e++) S[tn][e] = 0.f;

    #pragma unroll
    for (int tnp = 0; tnp < 4; tnp++) {
        #pragma unroll
        for (int ks = 0; ks < 2; ks++) {
            uint32_t kb[4];
            ldmat_x4(kb, smem_u32(ksm + (tnp*16 + b_roff)*40 + ks*16 + b_koff));
            mma_bf16(S[2*tnp],   qa[ks][0], qa[ks][1], qa[ks][2], qa[ks][3], kb[0], kb[1]);
            mma_bf16(S[2*tnp+1], qa[ks][0], qa[ks][1], qa[ks][2], qa[ks][3], kb[2], kb[3]);
        }
    }

    int r0 = wid*16 + g, r1 = r0 + 8;
    int reg0 = regid[r0], reg1 = regid[r1];
    float mx0 = -1e30f, mx1 = -1e30f;
    #pragma unroll
    for (int tn = 0; tn < 8; tn++) {
        #pragma unroll
        for (int e = 0; e < 4; e++) {
            int p  = (e < 2) ? r0 : r1;
            int qq = tn*8 + ct*2 + (e & 1);
            int dx = (p & 7) - (qq & 7);
            int dy = (p >> 3) - (qq >> 3);
            float bias = rpbh[(dx + 7)*15 + (dy + 7)];
            float v = S[tn][e]*QSCALE + bias;
            if (((e < 2) ? reg0 : reg1) == regid[qq]) v -= 100.f;
            S[tn][e] = v;
            if (e < 2) mx0 = fmaxf(mx0, v); else mx1 = fmaxf(mx1, v);
        }
    }
    #pragma unroll
    for (int off = 1; off <= 2; off <<= 1) {
        mx0 = fmaxf(mx0, __shfl_xor_sync(0xffffffffu, mx0, off));
        mx1 = fmaxf(mx1, __shfl_xor_sync(0xffffffffu, mx1, off));
    }
    float sm0 = 0.f, sm1 = 0.f;
    #pragma unroll
    for (int tn = 0; tn < 8; tn++) {
        S[tn][0] = __expf(S[tn][0] - mx0); sm0 += S[tn][0];
        S[tn][1] = __expf(S[tn][1] - mx0); sm0 += S[tn][1];
        S[tn][2] = __expf(S[tn][2] - mx1); sm1 += S[tn][2];
        S[tn][3] = __expf(S[tn][3] - mx1); sm1 += S[tn][3];
    }
    #pragma unroll
    for (int off = 1; off <= 2; off <<= 1) {
        sm0 += __shfl_xor_sync(0xffffffffu, sm0, off);
        sm1 += __shfl_xor_sync(0xffffffffu, sm1, off);
    }
    float inv0 = 1.f / sm0, inv1 = 1.f / sm1;

    float O[4][4];
    #pragma unroll
    for (int dn = 0; dn < 4; dn++)
        #pragma unroll
        for (int e = 0; e < 4; e++) O[dn][e] = 0.f;

    #pragma unroll
    for (int kt = 0; kt < 4; kt++) {
        uint32_t pa0 = pack_bf16x2(S[2*kt][0],   S[2*kt][1]);
        uint32_t pa1 = pack_bf16x2(S[2*kt][2],   S[2*kt][3]);
        uint32_t pa2 = pack_bf16x2(S[2*kt+1][0], S[2*kt+1][1]);
        uint32_t pa3 = pack_bf16x2(S[2*kt+1][2], S[2*kt+1][3]);
        #pragma unroll
        for (int dnp = 0; dnp < 2; dnp++) {
            uint32_t vb[4];
            ldmat_x4(vb, smem_u32(vt + (dnp*16 + b_roff)*72 + kt*16 + b_koff));
            mma_bf16(O[2*dnp],   pa0, pa1, pa2, pa3, vb[0], vb[1]);
            mma_bf16(O[2*dnp+1], pa0, pa1, pa2, pa3, vb[2], vb[3]);
        }
    }

    size_t row0 = (size_t)(widx*64 + r0);
    size_t row1 = (size_t)(widx*64 + r1);
    #pragma unroll
    for (int dn = 0; dn < 4; dn++) {
        int col = head*32 + dn*8 + ct*2;
        *(__nv_bfloat162*)(out + row0*DIMC + col) =
            __floats2bfloat162_rn(O[dn][0]*inv0, O[dn][1]*inv0);
        *(__nv_bfloat162*)(out + row1*DIMC + col) =
            __floats2bfloat162_rn(O[dn][2]*inv1, O[dn][3]*inv1);
    }
}

// ---------------------------------- launch --------------------------------------
extern "C" void kernel_launch(void* const* d_in, const int* in_sizes, int n_in,
                              void* d_out, int out_size)
{
    const float* x      = (const float*)d_in[0];
    const float* n1g    = (const float*)d_in[1];
    const float* n1b    = (const float*)d_in[2];
    const float* qkv_w  = (const float*)d_in[3];
    const float* qkv_b  = (const float*)d_in[4];
    const float* rpb    = (const float*)d_in[5];
    const float* proj_w = (const float*)d_in[6];
    const float* proj_b = (const float*)d_in[7];
    const float* n2g    = (const float*)d_in[8];
    const float* n2b    = (const float*)d_in[9];
    const float* fc1_w  = (const float*)d_in[10];
    const float* fc1_b  = (const float*)d_in[11];
    const float* fc2_w  = (const float*)d_in[12];
    const float* fc2_b  = (const float*)d_in[13];
    float* out = (float*)d_out;

    bf16 *xw, *qkvbuf, *attn, *yn, *m1;
    bf16 *wt_qkv, *wt_proj, *wt_fc1, *wt_fc2;
    cudaGetSymbolAddress((void**)&xw,      g_xw);
    cudaGetSymbolAddress((void**)&qkvbuf,  g_qkv);
    cudaGetSymbolAddress((void**)&attn,    g_attn);
    cudaGetSymbolAddress((void**)&yn,      g_yn);
    cudaGetSymbolAddress((void**)&m1,      g_m1);
    cudaGetSymbolAddress((void**)&wt_qkv,  g_wt_qkv);
    cudaGetSymbolAddress((void**)&wt_proj, g_wt_proj);
    cudaGetSymbolAddress((void**)&wt_fc1,  g_wt_fc1);
    cudaGetSymbolAddress((void**)&wt_fc2,  g_wt_fc2);

    const int SMEM = 6 * ASTG2;   // 110592 B
    cudaFuncSetAttribute((mma_gemm<0, bf16>),  cudaFuncAttributeMaxDynamicSharedMemorySize, SMEM);
    cudaFuncSetAttribute((mma_gemm<1, bf16>),  cudaFuncAttributeMaxDynamicSharedMemorySize, SMEM);
    cudaFuncSetAttribute((mma_gemm<3, float>), cudaFuncAttributeMaxDynamicSharedMemorySize, SMEM);
    const int PSMEM = 3 * PSTG;  // 92160 B
    cudaFuncSetAttribute(proj_ln_kernel, cudaFuncAttributeMaxDynamicSharedMemorySize, PSMEM);

    // merged weight transposes (192 + 64 + 256 + 256 blocks)
    transpose_all<<<768, dim3(32, 8)>>>(qkv_w, wt_qkv, proj_w, wt_proj,
                                        fc1_w, wt_fc1, fc2_w, wt_fc2);

    // 1) LN1 + cyclic shift + window partition (bf16 out)
    ln_kernel<<<ROWS/8, 256>>>(x, n1g, n1b, xw, 1);
    // 2) QKV GEMM: [65536,256] @ [256,768] -> bf16
    mma_gemm<0, bf16><<<dim3(768/128, ROWS/128), 256, SMEM>>>(xw, wt_qkv, qkv_b, nullptr,
                                                              qkvbuf, ROWS, 768, 256);
    // 3) windowed attention (tensor cores) -> bf16
    attn_kernel<<<ROWS/64*HEADS, 128>>>(qkvbuf, rpb, attn);
    // 4) proj GEMM + scatter + residual(x) + LN2 fused -> yn (bf16)
    proj_ln_kernel<<<ROWS/128, 256, PSMEM>>>(attn, wt_proj, proj_b, x, n2g, n2b, yn);
    // 5) fc1 + exact GELU -> bf16
    mma_gemm<1, bf16><<<dim3(1024/128, ROWS/128), 256, SMEM>>>(yn, wt_fc1, fc1_b, nullptr,
                                                               m1, ROWS, 1024, 256);
    // 6) fc2 + residual with ORIGINAL shortcut x -> out (fp32)
    mma_gemm<3, float><<<dim3(256/128, ROWS/128), 256, SMEM>>>(m1, wt_fc2, fc2_b, x,
                                                               out, ROWS, 256, 1024);
}